// round 6
// baseline (speedup 1.0000x reference)
#include <cuda_runtime.h>

#define DIMC 512
#define DIMK 128
#define HW   49
#define NSUP 25
#define NSAMP 26
#define NCOL (NSAMP * HW)          // 1274
#define PSTRIDE (NCOL * 256)       // one split-K partial plane

// Scratch (allocation-free)
__device__ float g_part[4 * PSTRIDE];     // [ks][(s*49+p)*256 + m]
__device__ float g_qq[HW * DIMK];         // [p][o]
__device__ float g_qv[HW * DIMK];         // [p][o]
__device__ float g_sk[NSUP * HW * DIMK];  // [(s*49+p)][o]  (0.5x applied)
__device__ float g_sv[NSUP * HW * DIMK];
__device__ float g_eu[NSUP * HW];         // per-(ng,pt) euclid partials
__device__ int   g_cnt[NSUP];             // kernelB arrival counters (self-resetting)
__device__ int   g_cntA[NSAMP * 4];       // kernelA (s,mt) arrival counters over ks

// ---- packed fp32x2 helpers (sm_10x) --------------------------------------
__device__ __forceinline__ unsigned long long pack2(float a, float b) {
    unsigned long long r;
    asm("mov.b64 %0, {%1, %2};" : "=l"(r) : "f"(a), "f"(b));
    return r;
}
__device__ __forceinline__ void fma2(unsigned long long& d,
                                     unsigned long long a, unsigned long long b) {
    asm("fma.rn.f32x2 %0, %1, %2, %0;" : "+l"(d) : "l"(a), "l"(b));
}
__device__ __forceinline__ float2 unpack2(unsigned long long v) {
    float2 f;
    asm("mov.b64 {%0, %1}, %2;" : "=f"(f.x), "=f"(f.y) : "l"(v));
    return f;
}

// ---------------------------------------------------------------------------
// Kernel A: split-K projection GEMM + fused split-K collapse in tail blocks.
//   Block (s, mt, ks): 64 rows x 49 pos x 128 c. 256 threads = 8 warps:
//     cg = warp>>2      : c half (0..63 / 64..127)  -> smem-reduced at end
//     ph = (warp>>1)&1  : 28-position slab
//     rh = warp&1       : 32-row half;  o = rh*32 + lane
//   W in smem row-major [o][132] -> LDS.128 gives w for 4 c.
//   Last ks-block per (s,mt) collapses the 4 partial planes (fused kernelR).
// ---------------------------------------------------------------------------
#define TPB_A 256
#define WPITCH 132
#define XPITCH 56

__global__ void __launch_bounds__(TPB_A, 3)
kernelA(const float* __restrict__ query, const float* __restrict__ supports,
        const float* __restrict__ Wqk, const float* __restrict__ Wv)
{
    extern __shared__ float sm[];
    float* Ws = sm;                    // [64 rows][WPITCH c]
    float* Xs = sm + 64 * WPITCH;      // [128 c][XPITCH pos]

    const int s  = blockIdx.x;         // 0..25 (25 == query)
    const int mt = blockIdx.y;         // 0..3
    const int ks = blockIdx.z;         // 0..3
    const int c0 = ks * 128;
    const float* W    = (mt < 2) ? Wqk : Wv;
    const int wrow0   = (mt & 1) * 64;
    const float* X    = (s == NSUP) ? query : supports + (size_t)s * DIMC * HW;

    const int tid = threadIdx.x;

    // Stage W: [o][c] row-major (gmem coalesced along c; smem write contiguous)
    for (int e = tid; e < 64 * 128; e += TPB_A) {
        int o = e >> 7, c = e & 127;
        Ws[o * WPITCH + c] = W[(size_t)(wrow0 + o) * DIMC + c0 + c];
    }
    // Stage X: [c][pos], zero-pad pos 49..55
    for (int e = tid; e < 128 * XPITCH; e += TPB_A) {
        int c = e / XPITCH, p = e - c * XPITCH;
        Xs[e] = (p < HW) ? X[(size_t)(c0 + c) * HW + p] : 0.f;
    }
    __syncthreads();

    const int warp = tid >> 5, lane = tid & 31;
    const int cg = warp >> 2;
    const int ph = (warp >> 1) & 1;
    const int rh = warp & 1;
    const int o  = rh * 32 + lane;

    unsigned long long acc[14];
#pragma unroll
    for (int i = 0; i < 14; i++) acc[i] = 0ull;

    const float4* w4p = (const float4*)(Ws + o * WPITCH + cg * 64);
    const float*  xb  = Xs + (cg * 64) * XPITCH + ph * 28;

#pragma unroll 2
    for (int c4 = 0; c4 < 16; c4++) {
        float4 w4 = w4p[c4];
#pragma unroll
        for (int cc = 0; cc < 4; cc++) {
            float w = (cc == 0) ? w4.x : (cc == 1) ? w4.y : (cc == 2) ? w4.z : w4.w;
            unsigned long long w2 = pack2(w, w);
            const float* xr = xb + (c4 * 4 + cc) * XPITCH;
#pragma unroll
            for (int i = 0; i < 7; i++) {
                ulonglong2 xv = *(const ulonglong2*)(xr + i * 4);
                fma2(acc[2 * i],     w2, xv.x);
                fma2(acc[2 * i + 1], w2, xv.y);
            }
        }
    }

    // Cross-c-group reduction through smem (reuse Ws region)
    __syncthreads();
    float* Red = sm;                   // [128 threads][28]
    if (cg == 1) {
        float* r = Red + (tid & 127) * 28;
#pragma unroll
        for (int i = 0; i < 14; i++) {
            float2 v = unpack2(acc[i]);
            r[2 * i] = v.x; r[2 * i + 1] = v.y;
        }
    }
    __syncthreads();

    if (cg == 0) {
        const float* r = Red + tid * 28;
        const int m = mt * 64 + o;
        float* base = g_part + (size_t)ks * PSTRIDE + (size_t)(s * HW) * 256 + m;
#pragma unroll
        for (int i = 0; i < 14; i++) {
            float2 v = unpack2(acc[i]);
            float v0 = v.x + r[2 * i];
            float v1 = v.y + r[2 * i + 1];
            int p0 = ph * 28 + 2 * i;
            if (p0 < HW)     base[(size_t)p0 * 256]       = v0;
            if (p0 + 1 < HW) base[(size_t)(p0 + 1) * 256] = v1;
        }
    }

    // ---- Fused split-K collapse: last ks-block per (s,mt) does kernelR work
    __shared__ int isLast;
    __syncthreads();                   // all epilogue stores issued
    if (tid == 0) {
        __threadfence();
        int old = atomicAdd(&g_cntA[s * 4 + mt], 1);
        isLast = (old == 3);
    }
    __syncthreads();

    if (isLast) {
        __threadfence();
        for (int e = tid; e < 64 * HW; e += TPB_A) {
            int p = e >> 6, m = e & 63;
            size_t idx = (size_t)(s * HW + p) * 256 + mt * 64 + m;
            float v = g_part[idx] + g_part[PSTRIDE + idx]
                    + g_part[2 * PSTRIDE + idx] + g_part[3 * PSTRIDE + idx];
            int gm = mt * 64 + m;          // 0..255
            int oo = gm & 127;
            if (s == NSUP) {
                if (gm < 128) g_qq[p * DIMK + oo] = v;
                else          g_qv[p * DIMK + oo] = v;
            } else {
                v *= 0.5f;                  // analytic sigmoid factor
                if (gm < 128) g_sk[(size_t)(s * HW + p) * DIMK + oo] = v;
                else          g_sv[(size_t)(s * HW + p) * DIMK + oo] = v;
            }
        }
        if (tid == 0) g_cntA[s * 4 + mt] = 0;   // reset for next replay
    }
}

// ---------------------------------------------------------------------------
// Kernel B: attention for a PAIR of query positions per block (as R5).
// ---------------------------------------------------------------------------
#define TPB_B 256
#define SIMP  256

__global__ void __launch_bounds__(TPB_B, 4)
kernelB(float* __restrict__ out, int n, int k)
{
    const int ng = blockIdx.x;
    const int pt = blockIdx.y;           // 0..24
    const int p0 = 2 * pt;
    const int np = (p0 + 1 < HW) ? 2 : 1;
    const int nkeys = k * HW;

    __shared__ float q0[DIMK], q1[DIMK];
    __shared__ float sims[2 * SIMP];
    __shared__ float osh[2 * DIMK];
    __shared__ float invsh[2];
    __shared__ float redsh[8];

    const int tid = threadIdx.x;
    const float SCALE = 0.08838834764831845f;  // 128^-0.5

    if (tid < DIMK) {
        q0[tid] = g_qq[p0 * DIMK + tid];
        q1[tid] = (np == 2) ? g_qq[(p0 + 1) * DIMK + tid] : 0.f;
    }
    __syncthreads();

    const float* skbase = g_sk + (size_t)(ng * k * HW) * DIMK;
    for (int j = tid; j < nkeys; j += TPB_B) {
        const float4* sk4 = (const float4*)(skbase + (size_t)j * DIMK);
        float a0 = 0.f, b0 = 0.f, a1 = 0.f, b1 = 0.f;
#pragma unroll
        for (int o4 = 0; o4 < 32; o4 += 2) {
            float4 x = sk4[o4], y = sk4[o4 + 1];
            float4 qa = *(const float4*)(q0 + o4 * 4);
            float4 qb = *(const float4*)(q0 + o4 * 4 + 4);
            a0 += x.x * qa.x + x.y * qa.y + x.z * qa.z + x.w * qa.w;
            b0 += y.x * qb.x + y.y * qb.y + y.z * qb.z + y.w * qb.w;
            float4 ra = *(const float4*)(q1 + o4 * 4);
            float4 rb = *(const float4*)(q1 + o4 * 4 + 4);
            a1 += x.x * ra.x + x.y * ra.y + x.z * ra.z + x.w * ra.w;
            b1 += y.x * rb.x + y.y * rb.y + y.z * rb.z + y.w * rb.w;
        }
        sims[j]        = (a0 + b0) * SCALE;
        sims[SIMP + j] = (a1 + b1) * SCALE;
    }
    __syncthreads();

    if (tid < 64) {
        int pl = tid >> 5, l = tid & 31;
        if (pl < np) {
            float* row = sims + pl * SIMP;
            float m = -1e30f;
            for (int j = l; j < nkeys; j += 32) m = fmaxf(m, row[j]);
#pragma unroll
            for (int off = 16; off; off >>= 1) m = fmaxf(m, __shfl_xor_sync(~0u, m, off));
            float sum = 0.f;
            for (int j = l; j < nkeys; j += 32) {
                float e = __expf(row[j] - m);
                row[j] = e;
                sum += e;
            }
#pragma unroll
            for (int off = 16; off; off >>= 1) sum += __shfl_xor_sync(~0u, sum, off);
            if (l == 0) invsh[pl] = 1.f / sum;
        }
    }
    __syncthreads();

    const int o  = tid & 127;
    const int hf = tid >> 7;
    const float* svbase = g_sv + (size_t)(ng * k * HW) * DIMK + o;
    float c0a = 0.f, c1a = 0.f;
    int j = hf;
    for (; j + 6 < nkeys; j += 8) {
        float v0 = svbase[(size_t)(j)     * DIMK];
        float v1 = svbase[(size_t)(j + 2) * DIMK];
        float v2 = svbase[(size_t)(j + 4) * DIMK];
        float v3 = svbase[(size_t)(j + 6) * DIMK];
        c0a += sims[j] * v0 + sims[j + 2] * v1 + sims[j + 4] * v2 + sims[j + 6] * v3;
        c1a += sims[SIMP + j] * v0 + sims[SIMP + j + 2] * v1
             + sims[SIMP + j + 4] * v2 + sims[SIMP + j + 6] * v3;
    }
    for (; j < nkeys; j += 2) {
        float v = svbase[(size_t)j * DIMK];
        c0a += sims[j] * v;
        c1a += sims[SIMP + j] * v;
    }

    if (hf == 0) { osh[o] = c0a; osh[DIMK + o] = c1a; }
    __syncthreads();
    if (hf == 1) { osh[o] += c0a; osh[DIMK + o] += c1a; }
    __syncthreads();

    float e2 = 0.f;
    if (tid < DIMK) {
        float d0 = g_qv[p0 * DIMK + tid] - osh[tid] * invsh[0];
        e2 = d0 * d0;
        if (np == 2) {
            float d1 = g_qv[(p0 + 1) * DIMK + tid] - osh[DIMK + tid] * invsh[1];
            e2 += d1 * d1;
        }
    }
#pragma unroll
    for (int off = 16; off; off >>= 1) e2 += __shfl_xor_sync(~0u, e2, off);
    if ((tid & 31) == 0) redsh[tid >> 5] = e2;
    __syncthreads();

    if (tid == 0) {
        float t = 0.f;
#pragma unroll
        for (int w = 0; w < 8; w++) t += redsh[w];
        g_eu[ng * 25 + pt] = t;
        __threadfence();
        int old = atomicAdd(&g_cnt[ng], 1);
        if (old == 24) {
            __threadfence();
            volatile float* ve = g_eu + ng * 25;
            float ssum = 0.f;
            for (int i = 0; i < 25; i++) ssum += ve[i];
            out[ng] = -ssum / 49.0f;
            g_cnt[ng] = 0;
        }
    }
}

// ---------------------------------------------------------------------------
extern "C" void kernel_launch(void* const* d_in, const int* in_sizes, int n_in,
                              void* d_out, int out_size)
{
    const float* query    = (const float*)d_in[0];
    const float* supports = (const float*)d_in[1];
    const float* Wqk      = (const float*)d_in[2];
    const float* Wv       = (const float*)d_in[3];
    float* out = (float*)d_out;

    int n = out_size;
    if (n <= 0 || n > NSUP) n = 5;
    int k = NSUP / n;

    const int smemA = (64 * WPITCH + 128 * XPITCH + 16) * sizeof(float);  // 62,528 B
    cudaFuncSetAttribute(kernelA, cudaFuncAttributeMaxDynamicSharedMemorySize, smemA);

    kernelA<<<dim3(NSAMP, 4, 4), TPB_A, smemA>>>(query, supports, Wqk, Wv);
    kernelB<<<dim3(n, 25), TPB_B>>>(out, n, k);
}

// round 7
// speedup vs baseline: 1.2340x; 1.2340x over previous
#include <cuda_runtime.h>

#define DIMC 512
#define DIMK 128
#define HW   49
#define NSUP 25
#define NSAMP 26
#define NCOL (NSAMP * HW)          // 1274
#define NKS  8                     // split-K planes
#define PSTRIDE (NCOL * 256)       // one split-K partial plane

// Scratch (allocation-free)
__device__ float g_part[NKS * PSTRIDE];   // [ks][(s*49+p)*256 + m]
__device__ float g_qq[HW * DIMK];         // [p][o]
__device__ float g_qv[HW * DIMK];         // [p][o]
__device__ float g_sk[NSUP * HW * DIMK];  // [(s*49+p)][o]  (0.5x applied)
__device__ float g_sv[NSUP * HW * DIMK];
__device__ float g_eu[NSUP * HW];         // per-(ng,p) euclid partials
__device__ int   g_cnt[NSUP];             // arrival counters (self-resetting)

// ---- packed fp32x2 helpers (sm_10x) --------------------------------------
__device__ __forceinline__ unsigned long long pack2(float a, float b) {
    unsigned long long r;
    asm("mov.b64 %0, {%1, %2};" : "=l"(r) : "f"(a), "f"(b));
    return r;
}
__device__ __forceinline__ void fma2(unsigned long long& d,
                                     unsigned long long a, unsigned long long b) {
    asm("fma.rn.f32x2 %0, %1, %2, %0;" : "+l"(d) : "l"(a), "l"(b));
}
__device__ __forceinline__ float2 unpack2(unsigned long long v) {
    float2 f;
    asm("mov.b64 {%0, %1}, %2;" : "=f"(f.x), "=f"(f.y) : "l"(v));
    return f;
}

// ---------------------------------------------------------------------------
// Kernel A: split-K(8) projection GEMM. Block (s, mt, ks): 64 rows x 49 pos
// x 64 c. 128 threads = 4 warps: rh=warp&1 -> 32-row half (lane = row),
// ph=warp>>1 -> 28-pos slab. W smem c-major pitch 65 (conflict-free LDS.32),
// X c-major pitch 56 (broadcast 16B loads). 14 packed f32x2 accs per lane.
// smem 31KB -> ~6-7 CTAs/SM.
// ---------------------------------------------------------------------------
#define TPB_A 128
#define KC    64     // c per block
#define WPITCH 65
#define XPITCH 56

__global__ void __launch_bounds__(TPB_A, 6)
kernelA(const float* __restrict__ query, const float* __restrict__ supports,
        const float* __restrict__ Wqk, const float* __restrict__ Wv)
{
    extern __shared__ float sm[];
    float* Ws = sm;                    // [KC c][WPITCH rows]
    float* Xs = sm + KC * WPITCH;      // [KC c][XPITCH pos]

    const int s  = blockIdx.x;         // 0..25 (25 == query)
    const int mt = blockIdx.y;         // 0..3
    const int ks = blockIdx.z;         // 0..7
    const int c0 = ks * KC;
    const float* W    = (mt < 2) ? Wqk : Wv;
    const int wrow0   = (mt & 1) * 64;
    const float* X    = (s == NSUP) ? query : supports + (size_t)s * DIMC * HW;

    const int tid = threadIdx.x;

    // Stage W: 64 rows x 64 c (coalesced along c; smem transpose conflict-free)
    for (int e = tid; e < 64 * KC; e += TPB_A) {
        int o = e >> 6, c = e & (KC - 1);
        Ws[c * WPITCH + o] = W[(size_t)(wrow0 + o) * DIMC + c0 + c];
    }
    // Stage X: 64 c x 56 pos (zero-pad 49..55)
    for (int e = tid; e < KC * XPITCH; e += TPB_A) {
        int c = e / XPITCH, p = e - c * XPITCH;
        Xs[e] = (p < HW) ? X[(size_t)(c0 + c) * HW + p] : 0.f;
    }
    __syncthreads();

    const int warp = tid >> 5, lane = tid & 31;
    const int rh = warp & 1;
    const int ph = warp >> 1;
    const int o  = rh * 32 + lane;

    const float* wb = Ws + o;
    const float* xb = Xs + ph * 28;

    unsigned long long acc[14];
#pragma unroll
    for (int i = 0; i < 14; i++) acc[i] = 0ull;

#pragma unroll 4
    for (int c = 0; c < KC; c++) {
        float w = wb[c * WPITCH];                    // conflict-free LDS.32
        unsigned long long w2 = pack2(w, w);
        const float* xr = xb + c * XPITCH;
#pragma unroll
        for (int i = 0; i < 7; i++) {
            ulonglong2 xv = *(const ulonglong2*)(xr + i * 4);  // broadcast
            fma2(acc[2 * i],     w2, xv.x);
            fma2(acc[2 * i + 1], w2, xv.y);
        }
    }

    // Epilogue: coalesced per-p stores (lanes consecutive m)
    const int m = mt * 64 + o;
    float* base = g_part + (size_t)ks * PSTRIDE + (size_t)(s * HW) * 256 + m;
#pragma unroll
    for (int i = 0; i < 14; i++) {
        float2 v = unpack2(acc[i]);
        int p0 = ph * 28 + 2 * i;
        if (p0 < HW)     base[(size_t)p0 * 256]       = v.x;
        if (p0 + 1 < HW) base[(size_t)(p0 + 1) * 256] = v.y;
    }
}

// ---------------------------------------------------------------------------
// Kernel R: collapse 8 split-K planes (coalesced; ~12MB L2 traffic).
// ---------------------------------------------------------------------------
__global__ void __launch_bounds__(256)
kernelR()
{
    const int nn = blockIdx.x;          // (s*49+p)
    const int m  = threadIdx.x;         // 0..255
    const size_t idx = (size_t)nn * 256 + m;
    float v = 0.f;
#pragma unroll
    for (int kp = 0; kp < NKS; kp++) v += g_part[(size_t)kp * PSTRIDE + idx];

    const int s = nn / HW;
    const int p = nn - s * HW;
    const int o = m & 127;
    if (s == NSUP) {
        if (m < 128) g_qq[p * DIMK + o] = v;
        else         g_qv[p * DIMK + o] = v;
    } else {
        v *= 0.5f;                      // analytic sigmoid factor
        if (m < 128) g_sk[(size_t)nn * DIMK + o] = v;
        else         g_sv[(size_t)nn * DIMK + o] = v;
    }
}

// ---------------------------------------------------------------------------
// Kernel B: attention, one block per (group ng, query position p).
//   Warp-per-key / lane-per-channel layout everywhere: every LDG.128 is a
//   coalesced 512B row segment (4 wavefronts, not 32). Fused final reduce.
// ---------------------------------------------------------------------------
#define TPB_B 256
#define NKMAX 1232    // max nkeys (n=1 -> 1225), padded

__global__ void __launch_bounds__(TPB_B, 6)
kernelB(float* __restrict__ out, int n, int k)
{
    const int ng = blockIdx.x;
    const int p  = blockIdx.y;           // 0..48
    const int nkeys = k * HW;            // 245 for n=5

    __shared__ float sims[NKMAX];
    __shared__ float osh[8 * DIMK];
    __shared__ float redsh[8];
    __shared__ float sInv;

    const int tid  = threadIdx.x;
    const int warp = tid >> 5, lane = tid & 31;
    const float SCALE = 0.08838834764831845f;  // 128^-0.5

    // q for this position: lane holds channels lane*4..+3 (same in all warps)
    const float4 q4 = *(const float4*)(g_qq + (size_t)p * DIMK + lane * 4);

    // ---- sims: warp-per-key, coalesced sk rows, shfl-reduce dot ----
    const float* skb = g_sk + (size_t)(ng * k * HW) * DIMK;
#pragma unroll 4
    for (int j = warp; j < nkeys; j += 8) {
        float4 x = *(const float4*)(skb + (size_t)j * DIMK + lane * 4);
        float d = x.x * q4.x + x.y * q4.y + x.z * q4.z + x.w * q4.w;
#pragma unroll
        for (int off = 16; off; off >>= 1) d += __shfl_xor_sync(~0u, d, off);
        if (lane == 0) sims[j] = d * SCALE;
    }
    __syncthreads();

    // ---- softmax stats (warp 0) ----
    if (warp == 0) {
        float m = -1e30f;
        for (int j = lane; j < nkeys; j += 32) m = fmaxf(m, sims[j]);
#pragma unroll
        for (int off = 16; off; off >>= 1) m = fmaxf(m, __shfl_xor_sync(~0u, m, off));
        float sum = 0.f;
        for (int j = lane; j < nkeys; j += 32) {
            float e = __expf(sims[j] - m);
            sims[j] = e;
            sum += e;
        }
#pragma unroll
        for (int off = 16; off; off >>= 1) sum += __shfl_xor_sync(~0u, sum, off);
        if (lane == 0) sInv = 1.f / sum;
    }
    __syncthreads();

    // ---- AV: warp-per-key, float4 accumulators per lane ----
    const float* svb = g_sv + (size_t)(ng * k * HW) * DIMK;
    float4 a = make_float4(0.f, 0.f, 0.f, 0.f);
#pragma unroll 4
    for (int j = warp; j < nkeys; j += 8) {
        float4 v = *(const float4*)(svb + (size_t)j * DIMK + lane * 4);
        float wgt = sims[j];              // smem broadcast
        a.x += wgt * v.x;  a.y += wgt * v.y;
        a.z += wgt * v.z;  a.w += wgt * v.w;
    }
    *(float4*)(osh + warp * DIMK + lane * 4) = a;
    __syncthreads();

    // ---- combine 8 warps + euclid partial ----
    float e2 = 0.f;
    if (tid < DIMK) {
        float ov = 0.f;
#pragma unroll
        for (int w = 0; w < 8; w++) ov += osh[w * DIMK + tid];
        float d = g_qv[(size_t)p * DIMK + tid] - ov * sInv;
        e2 = d * d;
    }
#pragma unroll
    for (int off = 16; off; off >>= 1) e2 += __shfl_xor_sync(~0u, e2, off);
    if (lane == 0) redsh[warp] = e2;
    __syncthreads();

    if (tid == 0) {
        float t = 0.f;
#pragma unroll
        for (int w = 0; w < 8; w++) t += redsh[w];
        g_eu[ng * HW + p] = t;
        __threadfence();
        int old = atomicAdd(&g_cnt[ng], 1);
        if (old == HW - 1) {              // last of 49 blocks for this group
            __threadfence();
            volatile float* ve = g_eu + ng * HW;
            float ssum = 0.f;
            for (int i = 0; i < HW; i++) ssum += ve[i];   // fixed order
            out[ng] = -ssum / 49.0f;
            g_cnt[ng] = 0;                // reset for next graph replay
        }
    }
}

// ---------------------------------------------------------------------------
extern "C" void kernel_launch(void* const* d_in, const int* in_sizes, int n_in,
                              void* d_out, int out_size)
{
    const float* query    = (const float*)d_in[0];
    const float* supports = (const float*)d_in[1];
    const float* Wqk      = (const float*)d_in[2];
    const float* Wv       = (const float*)d_in[3];
    float* out = (float*)d_out;

    int n = out_size;
    if (n <= 0 || n > NSUP) n = 5;
    int k = NSUP / n;

    const int smemA = (KC * WPITCH + KC * XPITCH) * sizeof(float);  // 30,976 B
    cudaFuncSetAttribute(kernelA, cudaFuncAttributeMaxDynamicSharedMemorySize, smemA);

    kernelA<<<dim3(NSAMP, 4, NKS), TPB_A, smemA>>>(query, supports, Wqk, Wv);
    kernelR<<<NCOL, 256>>>();
    kernelB<<<dim3(n, HW), TPB_B>>>(out, n, k);
}

// round 8
// speedup vs baseline: 1.2414x; 1.0060x over previous
#include <cuda_runtime.h>

#define DIMC 512
#define DIMK 128
#define HW   49
#define NSUP 25
#define NSAMP 26
#define NCOL (NSAMP * HW)          // 1274
#define NKS  8                     // split-K planes
#define PSTRIDE (NCOL * 256)       // one split-K partial plane

// Scratch (allocation-free)
__device__ float g_part[NKS * PSTRIDE];   // [ks][(s*49+p)*256 + m]
__device__ float g_qq[HW * DIMK];         // [p][o]
__device__ float g_qv[HW * DIMK];         // [p][o]
__device__ float g_sk[NSUP * HW * DIMK];  // [(s*49+p)][o]  (0.5x applied)
__device__ float g_sv[NSUP * HW * DIMK];
__device__ float g_eu[NSUP * 13];         // per-(ng,pt) euclid partials
__device__ int   g_cnt[NSUP];             // arrival counters (self-resetting)

// ---- packed fp32x2 helpers (sm_10x) --------------------------------------
__device__ __forceinline__ unsigned long long pack2(float a, float b) {
    unsigned long long r;
    asm("mov.b64 %0, {%1, %2};" : "=l"(r) : "f"(a), "f"(b));
    return r;
}
__device__ __forceinline__ void fma2(unsigned long long& d,
                                     unsigned long long a, unsigned long long b) {
    asm("fma.rn.f32x2 %0, %1, %2, %0;" : "+l"(d) : "l"(a), "l"(b));
}
__device__ __forceinline__ float2 unpack2(unsigned long long v) {
    float2 f;
    asm("mov.b64 {%0, %1}, %2;" : "=f"(f.x), "=f"(f.y) : "l"(v));
    return f;
}

// ---------------------------------------------------------------------------
// Kernel A: split-K(8) projection GEMM.
//   Block (s, mt, ks): 64 rows x 49 pos x 64 c. 128 threads = 4 warps:
//   warp = 16-position slab (4x16=64, zero-padded past 49);
//   lane = TWO rows (o=lane and o=lane+32)  -> x loads not duplicated.
//   Per (warp,c): 2 LDS.32(w, conflict-free) + 4 broadcast LDS.128(x)
//   feeding 16 FFMA2. 32 accumulator regs.
// ---------------------------------------------------------------------------
#define TPB_A 128
#define KC    64     // c per block
#define WPITCH 65    // Ws[c][row], 65 = conflict-free
#define XPITCH 64    // Xs[c][pos]

__global__ void __launch_bounds__(TPB_A, 6)
kernelA(const float* __restrict__ query, const float* __restrict__ supports,
        const float* __restrict__ Wqk, const float* __restrict__ Wv)
{
    extern __shared__ float sm[];
    float* Ws = sm;                    // [KC c][WPITCH rows]
    float* Xs = sm + KC * WPITCH;      // [KC c][XPITCH pos]

    const int s  = blockIdx.x;         // 0..25 (25 == query)
    const int mt = blockIdx.y;         // 0..3
    const int ks = blockIdx.z;         // 0..7
    const int c0 = ks * KC;
    const float* W    = (mt < 2) ? Wqk : Wv;
    const int wrow0   = (mt & 1) * 64;
    const float* X    = (s == NSUP) ? query : supports + (size_t)s * DIMC * HW;

    const int tid = threadIdx.x;

    // Stage W: 64 rows x 64 c (gmem coalesced along c; transpose conflict-free)
    for (int e = tid; e < 64 * KC; e += TPB_A) {
        int o = e >> 6, c = e & (KC - 1);
        Ws[c * WPITCH + o] = W[(size_t)(wrow0 + o) * DIMC + c0 + c];
    }
    // Stage X: 64 c x 64 pos (zero-pad 49..63)
    for (int e = tid; e < KC * XPITCH; e += TPB_A) {
        int c = e >> 6, p = e & 63;
        Xs[e] = (p < HW) ? X[(size_t)(c0 + c) * HW + p] : 0.f;
    }
    __syncthreads();

    const int warp = tid >> 5, lane = tid & 31;   // warp = pos slab

    const float* wb0 = Ws + lane;          // row lane
    const float* wb1 = Ws + lane + 32;     // row lane+32
    const float* xb  = Xs + warp * 16;

    unsigned long long acc0[8], acc1[8];
#pragma unroll
    for (int i = 0; i < 8; i++) { acc0[i] = 0ull; acc1[i] = 0ull; }

#pragma unroll 4
    for (int c = 0; c < KC; c++) {
        float w0 = wb0[c * WPITCH];                  // conflict-free LDS.32
        float w1 = wb1[c * WPITCH];
        unsigned long long pw0 = pack2(w0, w0);
        unsigned long long pw1 = pack2(w1, w1);
        const float* xr = xb + c * XPITCH;
#pragma unroll
        for (int i = 0; i < 4; i++) {
            ulonglong2 xv = *(const ulonglong2*)(xr + i * 4);  // broadcast
            fma2(acc0[2 * i],     pw0, xv.x);
            fma2(acc0[2 * i + 1], pw0, xv.y);
            fma2(acc1[2 * i],     pw1, xv.x);
            fma2(acc1[2 * i + 1], pw1, xv.y);
        }
    }

    // Epilogue: coalesced per-p stores (lanes consecutive m)
    float* base = g_part + (size_t)ks * PSTRIDE + (size_t)(s * HW) * 256
                + mt * 64 + lane;
#pragma unroll
    for (int i = 0; i < 8; i++) {
        float2 v0 = unpack2(acc0[i]);
        float2 v1 = unpack2(acc1[i]);
        int p0 = warp * 16 + 2 * i;
        if (p0 < HW) {
            base[(size_t)p0 * 256]      = v0.x;
            base[(size_t)p0 * 256 + 32] = v1.x;
        }
        if (p0 + 1 < HW) {
            base[(size_t)(p0 + 1) * 256]      = v0.y;
            base[(size_t)(p0 + 1) * 256 + 32] = v1.y;
        }
    }
}

// ---------------------------------------------------------------------------
// Kernel R: collapse 8 split-K planes (coalesced; ~12MB L2 traffic).
// ---------------------------------------------------------------------------
__global__ void __launch_bounds__(256)
kernelR()
{
    const int nn = blockIdx.x;          // (s*49+p)
    const int m  = threadIdx.x;         // 0..255
    const size_t idx = (size_t)nn * 256 + m;
    float v = 0.f;
#pragma unroll
    for (int kp = 0; kp < NKS; kp++) v += g_part[(size_t)kp * PSTRIDE + idx];

    const int s = nn / HW;
    const int p = nn - s * HW;
    const int o = m & 127;
    if (s == NSUP) {
        if (m < 128) g_qq[p * DIMK + o] = v;
        else         g_qv[p * DIMK + o] = v;
    } else {
        v *= 0.5f;                      // analytic sigmoid factor
        if (m < 128) g_sk[(size_t)nn * DIMK + o] = v;
        else         g_sv[(size_t)nn * DIMK + o] = v;
    }
}

// ---------------------------------------------------------------------------
// Kernel B: attention, 4 query positions per block. Grid (n, 13).
//   Warp-per-key / lane-per-channel: one coalesced sk/sv row load feeds all
//   4 positions (4x traffic reuse vs R7). Fused final reduce via counters.
// ---------------------------------------------------------------------------
#define TPB_B 256
#define SIMP  1232    // sims row pitch (max nkeys = 1225 for n=1)

__global__ void __launch_bounds__(TPB_B)
kernelB(float* __restrict__ out, int n, int k)
{
    const int ng = blockIdx.x;
    const int pt = blockIdx.y;            // 0..12
    const int pb = pt * 4;                // first position
    const int np = (HW - pb < 4) ? (HW - pb) : 4;
    const int nkeys = k * HW;             // 245 for n=5

    extern __shared__ float bsm[];
    float* sims  = bsm;                   // [4][SIMP]
    float* osh   = bsm + 4 * SIMP;        // [8 warps][4 p][DIMK]
    float* invsh = osh + 8 * 4 * DIMK;    // [4]
    float* redsh = invsh + 4;             // [8]

    const int tid  = threadIdx.x;
    const int warp = tid >> 5, lane = tid & 31;
    const float SCALE = 0.08838834764831845f;  // 128^-0.5

    // q for up to 4 positions: lane holds channels lane*4..+3
    float4 q4[4];
#pragma unroll
    for (int i = 0; i < 4; i++) {
        q4[i] = (i < np)
              ? *(const float4*)(g_qq + (size_t)(pb + i) * DIMK + lane * 4)
              : make_float4(0.f, 0.f, 0.f, 0.f);
    }

    // ---- sims: warp-per-key, one coalesced row load -> 4 dots ----
    const float* skb = g_sk + (size_t)(ng * k * HW) * DIMK;
#pragma unroll 2
    for (int j = warp; j < nkeys; j += 8) {
        float4 x = *(const float4*)(skb + (size_t)j * DIMK + lane * 4);
        float d0 = x.x * q4[0].x + x.y * q4[0].y + x.z * q4[0].z + x.w * q4[0].w;
        float d1 = x.x * q4[1].x + x.y * q4[1].y + x.z * q4[1].z + x.w * q4[1].w;
        float d2 = x.x * q4[2].x + x.y * q4[2].y + x.z * q4[2].z + x.w * q4[2].w;
        float d3 = x.x * q4[3].x + x.y * q4[3].y + x.z * q4[3].z + x.w * q4[3].w;
#pragma unroll
        for (int off = 16; off; off >>= 1) {
            d0 += __shfl_xor_sync(~0u, d0, off);
            d1 += __shfl_xor_sync(~0u, d1, off);
            d2 += __shfl_xor_sync(~0u, d2, off);
            d3 += __shfl_xor_sync(~0u, d3, off);
        }
        if (lane == 0) {
            sims[j]            = d0 * SCALE;
            sims[SIMP + j]     = d1 * SCALE;
            sims[2 * SIMP + j] = d2 * SCALE;
            sims[3 * SIMP + j] = d3 * SCALE;
        }
    }
    __syncthreads();

    // ---- softmax stats: warp i handles position i ----
    if (warp < 4 && warp < np) {
        float* row = sims + warp * SIMP;
        float m = -1e30f;
        for (int j = lane; j < nkeys; j += 32) m = fmaxf(m, row[j]);
#pragma unroll
        for (int off = 16; off; off >>= 1) m = fmaxf(m, __shfl_xor_sync(~0u, m, off));
        float sum = 0.f;
        for (int j = lane; j < nkeys; j += 32) {
            float e = __expf(row[j] - m);
            row[j] = e;
            sum += e;
        }
#pragma unroll
        for (int off = 16; off; off >>= 1) sum += __shfl_xor_sync(~0u, sum, off);
        if (lane == 0) invsh[warp] = 1.f / sum;
    }
    __syncthreads();

    // ---- AV: warp-per-key, 4 float4 accumulators ----
    const float* svb = g_sv + (size_t)(ng * k * HW) * DIMK;
    float4 a0 = make_float4(0.f, 0.f, 0.f, 0.f), a1 = a0, a2 = a0, a3 = a0;
#pragma unroll 2
    for (int j = warp; j < nkeys; j += 8) {
        float4 v = *(const float4*)(svb + (size_t)j * DIMK + lane * 4);
        float w0 = sims[j], w1 = sims[SIMP + j];
        float w2 = sims[2 * SIMP + j], w3 = sims[3 * SIMP + j];
        a0.x += w0 * v.x; a0.y += w0 * v.y; a0.z += w0 * v.z; a0.w += w0 * v.w;
        a1.x += w1 * v.x; a1.y += w1 * v.y; a1.z += w1 * v.z; a1.w += w1 * v.w;
        a2.x += w2 * v.x; a2.y += w2 * v.y; a2.z += w2 * v.z; a2.w += w2 * v.w;
        a3.x += w3 * v.x; a3.y += w3 * v.y; a3.z += w3 * v.z; a3.w += w3 * v.w;
    }
    {
        float* ob = osh + (warp * 4) * DIMK + lane * 4;
        *(float4*)(ob)            = a0;
        *(float4*)(ob + DIMK)     = a1;
        *(float4*)(ob + 2 * DIMK) = a2;
        *(float4*)(ob + 3 * DIMK) = a3;
    }
    __syncthreads();

    // ---- combine 8 warps + euclid partial over np positions ----
    float e2 = 0.f;
    if (tid < DIMK) {
#pragma unroll
        for (int i = 0; i < 4; i++) {
            if (i < np) {
                float ov = 0.f;
#pragma unroll
                for (int w = 0; w < 8; w++) ov += osh[(w * 4 + i) * DIMK + tid];
                float d = g_qv[(size_t)(pb + i) * DIMK + tid] - ov * invsh[i];
                e2 += d * d;
            }
        }
    }
#pragma unroll
    for (int off = 16; off; off >>= 1) e2 += __shfl_xor_sync(~0u, e2, off);
    if (lane == 0) redsh[warp] = e2;
    __syncthreads();

    if (tid == 0) {
        float t = 0.f;
#pragma unroll
        for (int w = 0; w < 8; w++) t += redsh[w];
        g_eu[ng * 13 + pt] = t;
        __threadfence();
        int old = atomicAdd(&g_cnt[ng], 1);
        if (old == 12) {                  // last of 13 blocks for this group
            __threadfence();
            volatile float* ve = g_eu + ng * 13;
            float ssum = 0.f;
            for (int i = 0; i < 13; i++) ssum += ve[i];   // fixed order
            out[ng] = -ssum / 49.0f;
            g_cnt[ng] = 0;                // reset for next graph replay
        }
    }
}

// ---------------------------------------------------------------------------
extern "C" void kernel_launch(void* const* d_in, const int* in_sizes, int n_in,
                              void* d_out, int out_size)
{
    const float* query    = (const float*)d_in[0];
    const float* supports = (const float*)d_in[1];
    const float* Wqk      = (const float*)d_in[2];
    const float* Wv       = (const float*)d_in[3];
    float* out = (float*)d_out;

    int n = out_size;
    if (n <= 0 || n > NSUP) n = 5;
    int k = NSUP / n;

    const int smemA = (KC * WPITCH + KC * XPITCH) * sizeof(float);  // 33,024 B
    cudaFuncSetAttribute(kernelA, cudaFuncAttributeMaxDynamicSharedMemorySize, smemA);

    const int smemB = (4 * SIMP + 8 * 4 * DIMK + 4 + 8) * sizeof(float); // ~36.2 KB
    cudaFuncSetAttribute(kernelB, cudaFuncAttributeMaxDynamicSharedMemorySize, smemB);

    kernelA<<<dim3(NSAMP, 4, NKS), TPB_A, smemA>>>(query, supports, Wqk, Wv);
    kernelR<<<NCOL, 256>>>();
    kernelB<<<dim3(n, 13), TPB_B, smemB>>>(out, n, k);
}